// round 10
// baseline (speedup 1.0000x reference)
#include <cuda_runtime.h>

// ---------------------------------------------------------------------------
// TinyMixedHeteroLinkPredictor — round 10: fused, register vectors +
// scalar-only smem LUT, 2 edges/thread, 2 gathers in flight.
//
//   logit(e) = feat[tab_s(t)][src] . v_src[t] + feat[tab_d(t)][dst] . v_dst[t] + c[t]
//
// Evidence-driven composition:
//  * folded vectors in REGISTERS (R5: smem vec/ptr LUT costs ~11 us via LDS
//    latency chains on the gather address path; R9/R6 regressions).
//  * flags + per-type constant via SCALAR smem LDS (R3: proven ~free).
//  * table pointer chosen by register SEL on flag (no pointer LDS).
//  * 2 edges/thread, gathers consumed per edge (2 in flight) -> ~40 live regs
//    for 6 blocks/SM without spilling (R5's 48 regs capped occ at 57%).
//  * __ldcs/__stcs streams (R5: DRAM 51% -> 36%), __ldg gathers.
// ---------------------------------------------------------------------------

__device__ __forceinline__ float dot4(float4 a, float4 b) {
    return a.x * b.x + a.y * b.y + a.z * b.z + a.w * b.w;
}

__global__ void __launch_bounds__(256, 6) fused_k(
    const float4* __restrict__ ax, const float4* __restrict__ px,
    const int* __restrict__ src, const int* __restrict__ dst,
    const int* __restrict__ typ, float* __restrict__ out, int E,
    const float* __restrict__ Wa, const float* __restrict__ ba,
    const float* __restrict__ Wp, const float* __restrict__ bp,
    const float* __restrict__ Ws, const float* __restrict__ bs,
    const int* __restrict__ fsrc, const int* __restrict__ fdst)
{
    __shared__ float  s_vec[16];   // vas | vps | vad | vpd (broadcast to regs once)
    __shared__ float  s_c[4];      // per-type constant
    __shared__ int    s_fs[4];     // per-type src-table flag
    __shared__ int    s_fd[4];     // per-type dst-table flag

    if (threadIdx.x == 0) {
#pragma unroll
        for (int j = 0; j < 4; j++) {
            float a = 0.f, p = 0.f, ad = 0.f, pd = 0.f;
#pragma unroll
            for (int i = 0; i < 4; i++) {
                float wsi = Ws[i], wsd = Ws[4 + i];
                float wa = Wa[i * 4 + j], wp = Wp[i * 4 + j];
                a  += wsi * wa;  p  += wsi * wp;
                ad += wsd * wa;  pd += wsd * wp;
            }
            s_vec[0 + j]  = a;   // vas
            s_vec[4 + j]  = p;   // vps
            s_vec[8 + j]  = ad;  // vad
            s_vec[12 + j] = pd;  // vpd
        }
        float cas = 0.f, cps = 0.f, cad = 0.f, cpd = 0.f;
#pragma unroll
        for (int i = 0; i < 4; i++) {
            cas += Ws[i]     * ba[i];
            cps += Ws[i]     * bp[i];
            cad += Ws[4 + i] * ba[i];
            cpd += Ws[4 + i] * bp[i];
        }
        float b0 = bs[0];
#pragma unroll
        for (int t = 0; t < 4; t++) {
            int fsv = fsrc[t], fdv = fdst[t];
            s_fs[t] = fsv;
            s_fd[t] = fdv;
            s_c[t]  = b0 + (fsv ? cps : cas) + (fdv ? cpd : cad);
        }
    }
    __syncthreads();

    // One-time uniform broadcast of the folded vectors into registers.
    const float4 vas = make_float4(s_vec[0],  s_vec[1],  s_vec[2],  s_vec[3]);
    const float4 vps = make_float4(s_vec[4],  s_vec[5],  s_vec[6],  s_vec[7]);
    const float4 vad = make_float4(s_vec[8],  s_vec[9],  s_vec[10], s_vec[11]);
    const float4 vpd = make_float4(s_vec[12], s_vec[13], s_vec[14], s_vec[15]);

    int i = blockIdx.x * blockDim.x + threadIdx.x;
    int base = i * 2;
    if (base + 1 < E) {
        int2 s2 = __ldcs(reinterpret_cast<const int2*>(src) + i);
        int2 d2 = __ldcs(reinterpret_cast<const int2*>(dst) + i);
        int2 t2 = __ldcs(reinterpret_cast<const int2*>(typ) + i);

        float2 o;
        {
            int t = t2.x;
            int fs = s_fs[t], fd = s_fd[t];
            float4 sf = __ldg((fs ? px : ax) + s2.x);
            float4 df = __ldg((fd ? px : ax) + d2.x);
            o.x = dot4(sf, fs ? vps : vas) + dot4(df, fd ? vpd : vad) + s_c[t];
        }
        {
            int t = t2.y;
            int fs = s_fs[t], fd = s_fd[t];
            float4 sf = __ldg((fs ? px : ax) + s2.y);
            float4 df = __ldg((fd ? px : ax) + d2.y);
            o.y = dot4(sf, fs ? vps : vas) + dot4(df, fd ? vpd : vad) + s_c[t];
        }
        __stcs(reinterpret_cast<float2*>(out) + i, o);
    } else if (base < E) {
        for (int e = base; e < E; e++) {
            int t = typ[e];
            int fs = s_fs[t], fd = s_fd[t];
            float4 sf = __ldg((fs ? px : ax) + src[e]);
            float4 df = __ldg((fd ? px : ax) + dst[e]);
            out[e] = dot4(sf, fs ? vps : vas) + dot4(df, fd ? vpd : vad) + s_c[t];
        }
    }
}

extern "C" void kernel_launch(void* const* d_in, const int* in_sizes, int n_in,
                              void* d_out, int out_size)
{
    const float* author_x = (const float*)d_in[0];
    const float* paper_x  = (const float*)d_in[1];
    const int*   src      = (const int*)  d_in[2];
    const int*   dst      = (const int*)  d_in[3];
    const int*   typ      = (const int*)  d_in[4];
    const int*   fsrc     = (const int*)  d_in[5];
    const int*   fdst     = (const int*)  d_in[6];
    const float* Wa       = (const float*)d_in[7];
    const float* ba       = (const float*)d_in[8];
    const float* Wp       = (const float*)d_in[9];
    const float* bp       = (const float*)d_in[10];
    const float* Ws       = (const float*)d_in[11];
    const float* bs       = (const float*)d_in[12];

    int E = in_sizes[2];
    int pairs = (E + 1) / 2;
    int eb = (pairs + 255) / 256;
    fused_k<<<eb, 256>>>((const float4*)author_x, (const float4*)paper_x,
                         src, dst, typ, (float*)d_out, E,
                         Wa, ba, Wp, bp, Ws, bs, fsrc, fdst);
}

// round 11
// speedup vs baseline: 1.0888x; 1.0888x over previous
#include <cuda_runtime.h>

// ---------------------------------------------------------------------------
// TinyMixedHeteroLinkPredictor — round 11: R5 structure (best fused: 143.8),
// concurrency raised via 128-thread blocks + __launch_bounds__(128, 12).
//
//   logit(e) = feat[tab_s(t)][src] . v_src[t] + feat[tab_d(t)][dst] . v_dst[t] + c[t]
//
// Model (falsified R6 story): limiter = gathers-in-flight per SM
//   (occ x threads x outstanding 16B gathers/thread). R5: 57% x 4 -> 4.7K.
//   This round: 75% x 4 -> 6.1K (+32%), by capping regs at 42 (spill lands on
//   results/tail state, not the gather chain).
// Kept from evidence: register folded vectors (R9: smem vec/ptr LUT -11us),
// 4 edges/thread int4 streams, pairwise gather consumption, __ldcs/__stcs.
// ---------------------------------------------------------------------------

__device__ __forceinline__ float dot4(float4 a, float4 b) {
    return a.x * b.x + a.y * b.y + a.z * b.z + a.w * b.w;
}

struct Folded {
    float4 vas, vps, vad, vpd;
    float  c[4];
    int    fs[4], fd[4];
};

__global__ void __launch_bounds__(128, 12) fused_k(
    const float4* __restrict__ ax, const float4* __restrict__ px,
    const int* __restrict__ src, const int* __restrict__ dst,
    const int* __restrict__ typ, float* __restrict__ out, int E,
    const float* __restrict__ Wa, const float* __restrict__ ba,
    const float* __restrict__ Wp, const float* __restrict__ bp,
    const float* __restrict__ Ws, const float* __restrict__ bs,
    const int* __restrict__ fsrc, const int* __restrict__ fdst)
{
    __shared__ Folded F;
    if (threadIdx.x == 0) {
        float vas[4], vps[4], vad[4], vpd[4];
#pragma unroll
        for (int j = 0; j < 4; j++) {
            float a = 0.f, p = 0.f, ad = 0.f, pd = 0.f;
#pragma unroll
            for (int i = 0; i < 4; i++) {
                float wsi = Ws[i], wsd = Ws[4 + i];
                float wa = Wa[i * 4 + j], wp = Wp[i * 4 + j];
                a  += wsi * wa;  p  += wsi * wp;
                ad += wsd * wa;  pd += wsd * wp;
            }
            vas[j] = a; vps[j] = p; vad[j] = ad; vpd[j] = pd;
        }
        F.vas = make_float4(vas[0], vas[1], vas[2], vas[3]);
        F.vps = make_float4(vps[0], vps[1], vps[2], vps[3]);
        F.vad = make_float4(vad[0], vad[1], vad[2], vad[3]);
        F.vpd = make_float4(vpd[0], vpd[1], vpd[2], vpd[3]);
        float cas = 0.f, cps = 0.f, cad = 0.f, cpd = 0.f;
#pragma unroll
        for (int i = 0; i < 4; i++) {
            cas += Ws[i]     * ba[i];
            cps += Ws[i]     * bp[i];
            cad += Ws[4 + i] * ba[i];
            cpd += Ws[4 + i] * bp[i];
        }
        float b0 = bs[0];
#pragma unroll
        for (int t = 0; t < 4; t++) {
            int s = fsrc[t], d = fdst[t];
            F.fs[t] = s;
            F.fd[t] = d;
            F.c[t]  = b0 + (s ? cps : cas) + (d ? cpd : cad);
        }
    }
    __syncthreads();

    const float4 vas = F.vas, vps = F.vps, vad = F.vad, vpd = F.vpd;

    int i = blockIdx.x * blockDim.x + threadIdx.x;
    int base = i * 4;
    if (base + 3 < E) {
        int4 s4 = __ldcs(reinterpret_cast<const int4*>(src) + i);
        int4 d4 = __ldcs(reinterpret_cast<const int4*>(dst) + i);
        int4 t4 = __ldcs(reinterpret_cast<const int4*>(typ) + i);

        int se[4] = {s4.x, s4.y, s4.z, s4.w};
        int de[4] = {d4.x, d4.y, d4.z, d4.w};
        int te[4] = {t4.x, t4.y, t4.z, t4.w};

        float r[4];
#pragma unroll
        for (int pair = 0; pair < 2; pair++) {
            int k0 = pair * 2, k1 = k0 + 1;
            int fs0 = F.fs[te[k0]], fd0 = F.fd[te[k0]];
            int fs1 = F.fs[te[k1]], fd1 = F.fd[te[k1]];
            // 4 gathers in flight
            float4 sf0 = __ldg((fs0 ? px : ax) + se[k0]);
            float4 df0 = __ldg((fd0 ? px : ax) + de[k0]);
            float4 sf1 = __ldg((fs1 ? px : ax) + se[k1]);
            float4 df1 = __ldg((fd1 ? px : ax) + de[k1]);
            r[k0] = dot4(sf0, fs0 ? vps : vas) + dot4(df0, fd0 ? vpd : vad) + F.c[te[k0]];
            r[k1] = dot4(sf1, fs1 ? vps : vas) + dot4(df1, fd1 ? vpd : vad) + F.c[te[k1]];
        }

        __stcs(reinterpret_cast<float4*>(out) + i,
               make_float4(r[0], r[1], r[2], r[3]));
    } else if (base < E) {
        for (int e = base; e < E; e++) {
            int t = typ[e];
            int s = src[e], d = dst[e];
            const float4* sb = F.fs[t] ? px : ax;
            const float4* db = F.fd[t] ? px : ax;
            float4 vs = F.fs[t] ? vps : vas;
            float4 vd = F.fd[t] ? vpd : vad;
            out[e] = dot4(__ldg(&sb[s]), vs) + dot4(__ldg(&db[d]), vd) + F.c[t];
        }
    }
}

extern "C" void kernel_launch(void* const* d_in, const int* in_sizes, int n_in,
                              void* d_out, int out_size)
{
    const float* author_x = (const float*)d_in[0];
    const float* paper_x  = (const float*)d_in[1];
    const int*   src      = (const int*)  d_in[2];
    const int*   dst      = (const int*)  d_in[3];
    const int*   typ      = (const int*)  d_in[4];
    const int*   fsrc     = (const int*)  d_in[5];
    const int*   fdst     = (const int*)  d_in[6];
    const float* Wa       = (const float*)d_in[7];
    const float* ba       = (const float*)d_in[8];
    const float* Wp       = (const float*)d_in[9];
    const float* bp       = (const float*)d_in[10];
    const float* Ws       = (const float*)d_in[11];
    const float* bs       = (const float*)d_in[12];

    int E = in_sizes[2];
    int quads = (E + 3) / 4;
    int eb = (quads + 127) / 128;
    fused_k<<<eb, 128>>>((const float4*)author_x, (const float4*)paper_x,
                         src, dst, typ, (float*)d_out, E,
                         Wa, ba, Wp, bp, Ws, bs, fsrc, fdst);
}

// round 12
// speedup vs baseline: 1.0976x; 1.0081x over previous
#include <cuda_runtime.h>

// ---------------------------------------------------------------------------
// TinyMixedHeteroLinkPredictor — round 12: R5 structure (best: 143.8 total)
// + no-allocate stream policy (__ldcv indices, __stwt output).
//
//   logit(e) = feat[tab_s(t)][src] . v_src[t] + feat[tab_d(t)][dst] . v_dst[t] + c[t]
//
// Evidence:
//  * R5 (48 regs, 57% occ) beats every higher-occupancy variant (R9/R10/R11)
//    -> latency already hidden; occupancy lever is dead.
//  * Residual: ~160 MB/replay of table-gather DRAM misses (DRAM 36%) from L2
//    contention with 268 MB/replay of single-use stream traffic.
//  * Fix: streams get ZERO L2 allocation — indices via ld.global.cv (read
//    once, no reuse), output via st.global.wt (write-through). L2 becomes a
//    dedicated 64 MB-table cache, persistent across graph replays.
// ---------------------------------------------------------------------------

__device__ __forceinline__ float dot4(float4 a, float4 b) {
    return a.x * b.x + a.y * b.y + a.z * b.z + a.w * b.w;
}

struct Folded {
    float4 vas, vps, vad, vpd;
    float  c[4];
    int    fs[4], fd[4];
};

__global__ void __launch_bounds__(256) fused_k(
    const float4* __restrict__ ax, const float4* __restrict__ px,
    const int* __restrict__ src, const int* __restrict__ dst,
    const int* __restrict__ typ, float* __restrict__ out, int E,
    const float* __restrict__ Wa, const float* __restrict__ ba,
    const float* __restrict__ Wp, const float* __restrict__ bp,
    const float* __restrict__ Ws, const float* __restrict__ bs,
    const int* __restrict__ fsrc, const int* __restrict__ fdst)
{
    __shared__ Folded F;
    if (threadIdx.x == 0) {
        float vas[4], vps[4], vad[4], vpd[4];
#pragma unroll
        for (int j = 0; j < 4; j++) {
            float a = 0.f, p = 0.f, ad = 0.f, pd = 0.f;
#pragma unroll
            for (int i = 0; i < 4; i++) {
                float wsi = Ws[i], wsd = Ws[4 + i];
                float wa = Wa[i * 4 + j], wp = Wp[i * 4 + j];
                a  += wsi * wa;  p  += wsi * wp;
                ad += wsd * wa;  pd += wsd * wp;
            }
            vas[j] = a; vps[j] = p; vad[j] = ad; vpd[j] = pd;
        }
        F.vas = make_float4(vas[0], vas[1], vas[2], vas[3]);
        F.vps = make_float4(vps[0], vps[1], vps[2], vps[3]);
        F.vad = make_float4(vad[0], vad[1], vad[2], vad[3]);
        F.vpd = make_float4(vpd[0], vpd[1], vpd[2], vpd[3]);
        float cas = 0.f, cps = 0.f, cad = 0.f, cpd = 0.f;
#pragma unroll
        for (int i = 0; i < 4; i++) {
            cas += Ws[i]     * ba[i];
            cps += Ws[i]     * bp[i];
            cad += Ws[4 + i] * ba[i];
            cpd += Ws[4 + i] * bp[i];
        }
        float b0 = bs[0];
#pragma unroll
        for (int t = 0; t < 4; t++) {
            int s = fsrc[t], d = fdst[t];
            F.fs[t] = s;
            F.fd[t] = d;
            F.c[t]  = b0 + (s ? cps : cas) + (d ? cpd : cad);
        }
    }
    __syncthreads();

    const float4 vas = F.vas, vps = F.vps, vad = F.vad, vpd = F.vpd;

    int i = blockIdx.x * blockDim.x + threadIdx.x;
    int base = i * 4;
    if (base + 3 < E) {
        // No-allocate reads: single-use stream data, keep it out of L2.
        int4 s4 = __ldcv(reinterpret_cast<const int4*>(src) + i);
        int4 d4 = __ldcv(reinterpret_cast<const int4*>(dst) + i);
        int4 t4 = __ldcv(reinterpret_cast<const int4*>(typ) + i);

        int se[4] = {s4.x, s4.y, s4.z, s4.w};
        int de[4] = {d4.x, d4.y, d4.z, d4.w};
        int te[4] = {t4.x, t4.y, t4.z, t4.w};

        float r[4];
#pragma unroll
        for (int pair = 0; pair < 2; pair++) {
            int k0 = pair * 2, k1 = k0 + 1;
            int fs0 = F.fs[te[k0]], fd0 = F.fd[te[k0]];
            int fs1 = F.fs[te[k1]], fd1 = F.fd[te[k1]];
            // 4 gathers in flight
            float4 sf0 = __ldg((fs0 ? px : ax) + se[k0]);
            float4 df0 = __ldg((fd0 ? px : ax) + de[k0]);
            float4 sf1 = __ldg((fs1 ? px : ax) + se[k1]);
            float4 df1 = __ldg((fd1 ? px : ax) + de[k1]);
            r[k0] = dot4(sf0, fs0 ? vps : vas) + dot4(df0, fd0 ? vpd : vad) + F.c[te[k0]];
            r[k1] = dot4(sf1, fs1 ? vps : vas) + dot4(df1, fd1 ? vpd : vad) + F.c[te[k1]];
        }

        // Write-through: no L2 allocation for the output stream.
        __stwt(reinterpret_cast<float4*>(out) + i,
               make_float4(r[0], r[1], r[2], r[3]));
    } else if (base < E) {
        for (int e = base; e < E; e++) {
            int t = typ[e];
            int s = src[e], d = dst[e];
            const float4* sb = F.fs[t] ? px : ax;
            const float4* db = F.fd[t] ? px : ax;
            float4 vs = F.fs[t] ? vps : vas;
            float4 vd = F.fd[t] ? vpd : vad;
            out[e] = dot4(__ldg(&sb[s]), vs) + dot4(__ldg(&db[d]), vd) + F.c[t];
        }
    }
}

extern "C" void kernel_launch(void* const* d_in, const int* in_sizes, int n_in,
                              void* d_out, int out_size)
{
    const float* author_x = (const float*)d_in[0];
    const float* paper_x  = (const float*)d_in[1];
    const int*   src      = (const int*)  d_in[2];
    const int*   dst      = (const int*)  d_in[3];
    const int*   typ      = (const int*)  d_in[4];
    const int*   fsrc     = (const int*)  d_in[5];
    const int*   fdst     = (const int*)  d_in[6];
    const float* Wa       = (const float*)d_in[7];
    const float* ba       = (const float*)d_in[8];
    const float* Wp       = (const float*)d_in[9];
    const float* bp       = (const float*)d_in[10];
    const float* Ws       = (const float*)d_in[11];
    const float* bs       = (const float*)d_in[12];

    int E = in_sizes[2];
    int quads = (E + 3) / 4;
    int eb = (quads + 255) / 256;
    fused_k<<<eb, 256>>>((const float4*)author_x, (const float4*)paper_x,
                         src, dst, typ, (float*)d_out, E,
                         Wa, ba, Wp, bp, Ws, bs, fsrc, fdst);
}

// round 16
// speedup vs baseline: 1.1115x; 1.0127x over previous
#include <cuda_runtime.h>

// ---------------------------------------------------------------------------
// TinyMixedHeteroLinkPredictor — round 16: R5 (best: 143.8) + L2 evict_last
// on table gathers via createpolicy + ld.global.nc.L2::cache_hint.v4.f32.
// (R13: bare .L2::evict_last modifier is 256-bit-only -> ptxas error.
//  R14/15: uint64_t without <cstdint> -> cudafe error. This round:
//  unsigned long long, no header dependency. Experiment unchanged.)
//
//   logit(e) = feat[tab_s(t)][src] . v_src[t] + feat[tab_d(t)][dst] . v_dst[t] + c[t]
//
// Evidence ledger:
//  * R5 (48 regs, 57% occ, 4 edges/thr, pairwise gathers, .cs streams) beats
//    all occupancy-raised variants (R9/R10/R11) -> latency already hidden.
//  * R12: .cv/.wt no-allocate streams raised DRAM to 50% -> streams want
//    evict-first allocation (.cs), not bypass.
//  * This round tests the one unmeasured lever: evict-last priority on the
//    64 MB tables so stream churn can't evict them (L2 persists across
//    graph replays).
// ---------------------------------------------------------------------------

__device__ __forceinline__ float dot4(float4 a, float4 b) {
    return a.x * b.x + a.y * b.y + a.z * b.z + a.w * b.w;
}

__device__ __forceinline__ unsigned long long make_evict_last_policy() {
    unsigned long long pol;
    asm("createpolicy.fractional.L2::evict_last.b64 %0, 1.0;" : "=l"(pol));
    return pol;
}

__device__ __forceinline__ float4 ldg_tab(const float4* p, unsigned long long pol) {
    float4 v;
    asm("ld.global.nc.L2::cache_hint.v4.f32 {%0,%1,%2,%3}, [%4], %5;"
        : "=f"(v.x), "=f"(v.y), "=f"(v.z), "=f"(v.w)
        : "l"(p), "l"(pol));
    return v;
}

struct Folded {
    float4 vas, vps, vad, vpd;
    float  c[4];
    int    fs[4], fd[4];
};

__global__ void __launch_bounds__(256) fused_k(
    const float4* __restrict__ ax, const float4* __restrict__ px,
    const int* __restrict__ src, const int* __restrict__ dst,
    const int* __restrict__ typ, float* __restrict__ out, int E,
    const float* __restrict__ Wa, const float* __restrict__ ba,
    const float* __restrict__ Wp, const float* __restrict__ bp,
    const float* __restrict__ Ws, const float* __restrict__ bs,
    const int* __restrict__ fsrc, const int* __restrict__ fdst)
{
    __shared__ Folded F;
    if (threadIdx.x == 0) {
        float vas[4], vps[4], vad[4], vpd[4];
#pragma unroll
        for (int j = 0; j < 4; j++) {
            float a = 0.f, p = 0.f, ad = 0.f, pd = 0.f;
#pragma unroll
            for (int i = 0; i < 4; i++) {
                float wsi = Ws[i], wsd = Ws[4 + i];
                float wa = Wa[i * 4 + j], wp = Wp[i * 4 + j];
                a  += wsi * wa;  p  += wsi * wp;
                ad += wsd * wa;  pd += wsd * wp;
            }
            vas[j] = a; vps[j] = p; vad[j] = ad; vpd[j] = pd;
        }
        F.vas = make_float4(vas[0], vas[1], vas[2], vas[3]);
        F.vps = make_float4(vps[0], vps[1], vps[2], vps[3]);
        F.vad = make_float4(vad[0], vad[1], vad[2], vad[3]);
        F.vpd = make_float4(vpd[0], vpd[1], vpd[2], vpd[3]);
        float cas = 0.f, cps = 0.f, cad = 0.f, cpd = 0.f;
#pragma unroll
        for (int i = 0; i < 4; i++) {
            cas += Ws[i]     * ba[i];
            cps += Ws[i]     * bp[i];
            cad += Ws[4 + i] * ba[i];
            cpd += Ws[4 + i] * bp[i];
        }
        float b0 = bs[0];
#pragma unroll
        for (int t = 0; t < 4; t++) {
            int s = fsrc[t], d = fdst[t];
            F.fs[t] = s;
            F.fd[t] = d;
            F.c[t]  = b0 + (s ? cps : cas) + (d ? cpd : cad);
        }
    }
    __syncthreads();

    const float4 vas = F.vas, vps = F.vps, vad = F.vad, vpd = F.vpd;
    const unsigned long long pol = make_evict_last_policy();

    int i = blockIdx.x * blockDim.x + threadIdx.x;
    int base = i * 4;
    if (base + 3 < E) {
        // Evict-first streams (R5-proven).
        int4 s4 = __ldcs(reinterpret_cast<const int4*>(src) + i);
        int4 d4 = __ldcs(reinterpret_cast<const int4*>(dst) + i);
        int4 t4 = __ldcs(reinterpret_cast<const int4*>(typ) + i);

        int se[4] = {s4.x, s4.y, s4.z, s4.w};
        int de[4] = {d4.x, d4.y, d4.z, d4.w};
        int te[4] = {t4.x, t4.y, t4.z, t4.w};

        float r[4];
#pragma unroll
        for (int pair = 0; pair < 2; pair++) {
            int k0 = pair * 2, k1 = k0 + 1;
            int fs0 = F.fs[te[k0]], fd0 = F.fd[te[k0]];
            int fs1 = F.fs[te[k1]], fd1 = F.fd[te[k1]];
            // 4 evict-last table gathers in flight.
            float4 sf0 = ldg_tab((fs0 ? px : ax) + se[k0], pol);
            float4 df0 = ldg_tab((fd0 ? px : ax) + de[k0], pol);
            float4 sf1 = ldg_tab((fs1 ? px : ax) + se[k1], pol);
            float4 df1 = ldg_tab((fd1 ? px : ax) + de[k1], pol);
            r[k0] = dot4(sf0, fs0 ? vps : vas) + dot4(df0, fd0 ? vpd : vad) + F.c[te[k0]];
            r[k1] = dot4(sf1, fs1 ? vps : vas) + dot4(df1, fd1 ? vpd : vad) + F.c[te[k1]];
        }

        __stcs(reinterpret_cast<float4*>(out) + i,
               make_float4(r[0], r[1], r[2], r[3]));
    } else if (base < E) {
        for (int e = base; e < E; e++) {
            int t = typ[e];
            int s = src[e], d = dst[e];
            const float4* sb = F.fs[t] ? px : ax;
            const float4* db = F.fd[t] ? px : ax;
            float4 vs = F.fs[t] ? vps : vas;
            float4 vd = F.fd[t] ? vpd : vad;
            out[e] = dot4(__ldg(&sb[s]), vs) + dot4(__ldg(&db[d]), vd) + F.c[t];
        }
    }
}

extern "C" void kernel_launch(void* const* d_in, const int* in_sizes, int n_in,
                              void* d_out, int out_size)
{
    const float* author_x = (const float*)d_in[0];
    const float* paper_x  = (const float*)d_in[1];
    const int*   src      = (const int*)  d_in[2];
    const int*   dst      = (const int*)  d_in[3];
    const int*   typ      = (const int*)  d_in[4];
    const int*   fsrc     = (const int*)  d_in[5];
    const int*   fdst     = (const int*)  d_in[6];
    const float* Wa       = (const float*)d_in[7];
    const float* ba       = (const float*)d_in[8];
    const float* Wp       = (const float*)d_in[9];
    const float* bp       = (const float*)d_in[10];
    const float* Ws       = (const float*)d_in[11];
    const float* bs       = (const float*)d_in[12];

    int E = in_sizes[2];
    int quads = (E + 3) / 4;
    int eb = (quads + 255) / 256;
    fused_k<<<eb, 256>>>((const float4*)author_x, (const float4*)paper_x,
                         src, dst, typ, (float*)d_out, E,
                         Wa, ba, Wp, bp, Ws, bs, fsrc, fdst);
}